// round 16
// baseline (speedup 1.0000x reference)
#include <cuda_runtime.h>
#include <cuda_fp16.h>
#include <cstdint>

// ---------------- problem constants -------------------------------------
#define B_    4
#define S_    8192
#define D_    2048
#define HD_   128
#define NTOK  (B_ * S_)            // 32768 tokens
#define NCOL  512                  // 4 projections * HD
#define NBLK  (B_ * (S_ / 4))      // 8192 output blocks
#define OUT_ELEMS (NBLK * HD_)     // 1048576

// GEMM tiling
#define BM 64
#define BN 256
#define BK 64
#define NKC (D_ / BK)              // 32 k-chunks

// ---------------- scratch (static device globals) ------------------------
__device__ __half g_Wt[NCOL * D_];                // 2 MB, K-major fp16 weights
__device__ __half g_C[(size_t)NTOK * NCOL];       // 32 MB GEMM output (fp16)

// ---------------- helpers ------------------------------------------------
__device__ __forceinline__ uint32_t smem_to_u32(const void* p) {
    uint32_t a;
    asm("{ .reg .u64 t; cvta.to.shared.u64 t, %1; cvt.u32.u64 %0, t; }"
        : "=r"(a) : "l"(p));
    return a;
}

// pack (k0, k1) -> f16x2 with k0 in the low half
__device__ __forceinline__ uint32_t pack2(float k0, float k1) {
    uint32_t r;
    asm("cvt.rn.f16x2.f32 %0, %1, %2;" : "=r"(r) : "f"(k1), "f"(k0));
    return r;
}

#define CP_ASYNC16(dst_u32, src_ptr) \
    asm volatile("cp.async.cg.shared.global [%0], [%1], 16;" \
                 :: "r"(dst_u32), "l"(src_ptr) : "memory")
#define CP_ASYNC_COMMIT() asm volatile("cp.async.commit_group;" ::: "memory")
#define CP_ASYNC_WAIT0()  asm volatile("cp.async.wait_group 0;" ::: "memory")

#define MMA_FP16(d, a, b) \
    asm volatile("mma.sync.aligned.m16n8k16.row.col.f32.f16.f16.f32 " \
                 "{%0,%1,%2,%3}, {%4,%5,%6,%7}, {%8,%9}, {%0,%1,%2,%3};" \
                 : "+f"((d)[0]), "+f"((d)[1]), "+f"((d)[2]), "+f"((d)[3]) \
                 : "r"((a)[0]), "r"((a)[1]), "r"((a)[2]), "r"((a)[3]), \
                   "r"((b)[0]), "r"((b)[1]))

#define LDMATRIX_X4(r0, r1, r2, r3, addr) \
    asm volatile("ldmatrix.sync.aligned.m8n8.x4.shared.b16 {%0,%1,%2,%3}, [%4];" \
                 : "=r"(r0), "=r"(r1), "=r"(r2), "=r"(r3) : "r"(addr))

// ---------------- smem layout (bytes): fp16 tiles, 128B rows padded to 144B
#define ROWB    144
#define A_PLANE (64 * ROWB)                // 9216 B
#define B_PLANE (256 * ROWB)               // 36864 B
#define STAGE   (A_PLANE + B_PLANE)        // 46080 B
#define OFF_A   0
#define OFF_B   A_PLANE
#define SMEM_BYTES (2 * STAGE)             // 92160 B

// ---------------- kernel 1: coalesced fp16 transpose of weights ----------
// g_Wt[n, k] = w_mat[k, j],  n = mat*128 + j
__global__ void prep_w_kernel(const float* __restrict__ wka,
                              const float* __restrict__ wkb,
                              const float* __restrict__ wza,
                              const float* __restrict__ wzb)
{
    __shared__ float tile[32][33];
    const int mat = blockIdx.z;
    const float* w = (mat == 0) ? wka : (mat == 1) ? wkb : (mat == 2) ? wza : wzb;
    const int k0 = blockIdx.x * 32;
    const int j0 = blockIdx.y * 32;
    const int tx = threadIdx.x;       // 0..31
    const int ty = threadIdx.y;       // 0..7

    #pragma unroll
    for (int i = 0; i < 32; i += 8)
        tile[ty + i][tx] = w[(size_t)(k0 + ty + i) * HD_ + j0 + tx];
    __syncthreads();
    #pragma unroll
    for (int i = 0; i < 32; i += 8)
        g_Wt[(size_t)(mat * HD_ + j0 + ty + i) * D_ + k0 + tx] =
            __float2half_rn(tile[tx][ty + i]);
}

// ---------------- kernel 2: pipelined fp16 mma.sync GEMM -----------------
// C[t, 0:512] = h[t, :] @ [Wkva | Wkvb | Wza | Wzb]
__global__ void __launch_bounds__(256, 2)
gemm_kernel(const float* __restrict__ h)
{
    extern __shared__ char sm[];
    const uint32_t smem_base = smem_to_u32(sm);

    const int tid    = threadIdx.x;
    const int lane   = tid & 31;
    const int wid    = tid >> 5;
    const int warp_m = wid >> 2;          // 0..1  (32 rows each)
    const int warp_n = wid & 3;           // 0..3  (64 cols each)

    const int t0 = (int)(blockIdx.x >> 1) * BM;
    const int n0 = (int)(blockIdx.x & 1) * BN;

    // A load coords: thread covers 16 contiguous k, one row
    const int arow = tid >> 2;            // 0..63
    const int akc  = tid & 3;             // 16-element k-chunk within 64
    const float* hrow = h + (size_t)(t0 + arow) * D_ + akc * 16;
    const uint32_t a_sts = (uint32_t)(arow * ROWB + akc * 32);

    uint32_t qa[8];

    // quantize 16 floats from hrow+off into qa
    auto loadquantA = [&](int koff) {
        #pragma unroll
        for (int i = 0; i < 4; ++i) {
            float4 v = *(const float4*)(hrow + koff + i * 4);
            qa[2 * i]     = pack2(v.x, v.y);
            qa[2 * i + 1] = pack2(v.z, v.w);
        }
    };

    // -------- prologue: stage 0 --------
    {
        loadquantA(0);
        #pragma unroll
        for (int j = 0; j < 8; ++j) {
            int e = tid + j * 256;
            int row = e >> 3, kc = e & 7;
            uint32_t dst = smem_base + OFF_B + (uint32_t)(row * ROWB + kc * 16);
            CP_ASYNC16(dst, g_Wt + (size_t)(n0 + row) * D_ + kc * 8);
        }
        CP_ASYNC_COMMIT();
        *(uint4*)(sm + OFF_A + a_sts)      = *(uint4*)(qa);
        *(uint4*)(sm + OFF_A + a_sts + 16) = *(uint4*)(qa + 4);
        CP_ASYNC_WAIT0();
        __syncthreads();
    }

    float acc[2][8][4];
    #pragma unroll
    for (int mt = 0; mt < 2; ++mt)
        #pragma unroll
        for (int nt = 0; nt < 8; ++nt)
            #pragma unroll
            for (int i = 0; i < 4; ++i) acc[mt][nt][i] = 0.0f;

    // ---- ldmatrix per-lane base addresses (stage offset added at use) ----
    // A tiles (m16k16, x4): lanes 0-7 rows m0-7 +0B; 8-15 rows m8-15 +0B;
    //                       16-23 rows m0-7 +16B; 24-31 rows m8-15 +16B
    const int aL_row = (lane & 7) + 8 * ((lane >> 3) & 1);
    const int aL_off = 16 * ((lane >> 4) & 1);
    uint32_t a_addr[2];
    #pragma unroll
    for (int mt = 0; mt < 2; ++mt)
        a_addr[mt] = smem_base + OFF_A +
                     (uint32_t)((warp_m * 32 + mt * 16 + aL_row) * ROWB + aL_off);

    // B tiles (two n8k16 per x4): matrices {nt+0B, nt+16B, nt+1+0B, nt+1+16B}
    const int bL_row = (lane & 7) + 8 * ((lane >> 4) & 1);   // which nt of the pair
    const int bL_off = 16 * ((lane >> 3) & 1);
    uint32_t b_addr[4];
    #pragma unroll
    for (int j = 0; j < 4; ++j)
        b_addr[j] = smem_base + OFF_B +
                    (uint32_t)((warp_n * 64 + j * 16 + bL_row) * ROWB + bL_off);

    for (int c = 0; c < NKC; ++c) {
        const int sb = (c & 1) * STAGE;
        const int nb = sb ^ STAGE;

        if (c + 1 < NKC) {
            const int k1 = (c + 1) * BK;
            loadquantA(k1);
            #pragma unroll
            for (int j = 0; j < 8; ++j) {
                int e = tid + j * 256;
                int row = e >> 3, kc = e & 7;
                uint32_t dst = smem_base + nb + OFF_B + (uint32_t)(row * ROWB + kc * 16);
                CP_ASYNC16(dst, g_Wt + (size_t)(n0 + row) * D_ + k1 + kc * 8);
            }
            CP_ASYNC_COMMIT();
        }

        // -------- compute on stage sb: 4 k16-steps --------
        #pragma unroll
        for (int ks = 0; ks < 4; ++ks) {
            const uint32_t ko = (uint32_t)sb + ks * 32;
            uint32_t af[2][4], bf[8][2];
            LDMATRIX_X4(af[0][0], af[0][1], af[0][2], af[0][3], a_addr[0] + ko);
            LDMATRIX_X4(af[1][0], af[1][1], af[1][2], af[1][3], a_addr[1] + ko);
            #pragma unroll
            for (int j = 0; j < 4; ++j)
                LDMATRIX_X4(bf[2 * j][0], bf[2 * j][1],
                            bf[2 * j + 1][0], bf[2 * j + 1][1], b_addr[j] + ko);
            #pragma unroll
            for (int mt = 0; mt < 2; ++mt)
                #pragma unroll
                for (int nt = 0; nt < 8; ++nt)
                    MMA_FP16(acc[mt][nt], af[mt], bf[nt]);
        }

        if (c + 1 < NKC) {
            *(uint4*)(sm + nb + OFF_A + a_sts)      = *(uint4*)(qa);
            *(uint4*)(sm + nb + OFF_A + a_sts + 16) = *(uint4*)(qa + 4);
            CP_ASYNC_WAIT0();
        }
        __syncthreads();
    }

    // -------- writeback (fp16) --------
    const int fr = lane >> 2;
    #pragma unroll
    for (int mt = 0; mt < 2; ++mt) {
        int r0 = t0 + warp_m * 32 + mt * 16 + fr;
        #pragma unroll
        for (int nt = 0; nt < 8; ++nt) {
            int cb = n0 + warp_n * 64 + nt * 8 + (lane & 3) * 2;
            *(uint32_t*)(g_C + (size_t)r0 * NCOL + cb) =
                pack2(acc[mt][nt][0], acc[mt][nt][1]);
            *(uint32_t*)(g_C + (size_t)(r0 + 8) * NCOL + cb) =
                pack2(acc[mt][nt][2], acc[mt][nt][3]);
        }
    }
}

// ---------------- kernel 3: masked softmax compression (4 feat/thread) ---
// C columns: [0,128)=c_a, [128,256)=c_b, [256,384)=z_a, [384,512)=z_b
__global__ void epilogue_kernel(const float* __restrict__ b_a,
                                const float* __restrict__ b_b,
                                float* __restrict__ out, int dup)
{
    int g4 = blockIdx.x * blockDim.x + threadIdx.x;   // 0..262143 (quads)
    int d  = (g4 & 31) * 4;    // feature index (multiple of 4)
    int bi = g4 >> 5;          // global block id 0..8191
    int i  = bi & 2047;        // block within batch
    int b  = bi >> 11;         // batch
    int t0 = b * S_ + i * 4;   // first token of current block

    float4 logit[8], val[8];
    const bool has_prev = (i > 0);
    #pragma unroll
    for (int j = 0; j < 4; ++j) {
        float4 bb4 = *(const float4*)(b_b + j * 128 + d);
        float4 ba4 = *(const float4*)(b_a + j * 128 + d);
        if (has_prev) {
            const __half* Cp = g_C + (size_t)(t0 - 4 + j) * NCOL;
            uint2 zr = *(const uint2*)(Cp + 384 + d);
            uint2 vr = *(const uint2*)(Cp + 128 + d);
            float2 z0 = __half22float2(*(__half2*)&zr.x);
            float2 z1 = __half22float2(*(__half2*)&zr.y);
            float2 v0 = __half22float2(*(__half2*)&vr.x);
            float2 v1 = __half22float2(*(__half2*)&vr.y);
            logit[j] = make_float4(z0.x + bb4.x, z0.y + bb4.y,
                                   z1.x + bb4.z, z1.y + bb4.w);
            val[j]   = make_float4(v0.x, v0.y, v1.x, v1.y);
        } else {
            logit[j] = make_float4(-3.0e38f, -3.0e38f, -3.0e38f, -3.0e38f);
            val[j]   = make_float4(0.0f, 0.0f, 0.0f, 0.0f);
        }
        const __half* Cc = g_C + (size_t)(t0 + j) * NCOL;
        uint2 zr = *(const uint2*)(Cc + 256 + d);
        uint2 vr = *(const uint2*)(Cc + d);
        float2 z0 = __half22float2(*(__half2*)&zr.x);
        float2 z1 = __half22float2(*(__half2*)&zr.y);
        float2 v0 = __half22float2(*(__half2*)&vr.x);
        float2 v1 = __half22float2(*(__half2*)&vr.y);
        logit[4 + j] = make_float4(z0.x + ba4.x, z0.y + ba4.y,
                                   z1.x + ba4.z, z1.y + ba4.w);
        val[4 + j]   = make_float4(v0.x, v0.y, v1.x, v1.y);
    }
    float mx0 = logit[0].x, mx1 = logit[0].y, mx2 = logit[0].z, mx3 = logit[0].w;
    #pragma unroll
    for (int j = 1; j < 8; ++j) {
        mx0 = fmaxf(mx0, logit[j].x); mx1 = fmaxf(mx1, logit[j].y);
        mx2 = fmaxf(mx2, logit[j].z); mx3 = fmaxf(mx3, logit[j].w);
    }
    float s0 = 0.f, s1 = 0.f, s2 = 0.f, s3 = 0.f;
    float a0 = 0.f, a1 = 0.f, a2 = 0.f, a3 = 0.f;
    #pragma unroll
    for (int j = 0; j < 8; ++j) {
        float e0 = __expf(logit[j].x - mx0);
        float e1 = __expf(logit[j].y - mx1);
        float e2 = __expf(logit[j].z - mx2);
        float e3 = __expf(logit[j].w - mx3);
        s0 += e0; s1 += e1; s2 += e2; s3 += e3;
        a0 += e0 * val[j].x; a1 += e1 * val[j].y;
        a2 += e2 * val[j].z; a3 += e3 * val[j].w;
    }
    float4 r = make_float4(a0 / s0, a1 / s1, a2 / s2, a3 / s3);
    int o = bi * 128 + d;
    *(float4*)(out + o) = r;
    if (dup) *(float4*)(out + o + OUT_ELEMS) = r;
}

// ---------------- launch ------------------------------------------------
extern "C" void kernel_launch(void* const* d_in, const int* in_sizes, int n_in,
                              void* d_out, int out_size)
{
    const float* h   = (const float*)d_in[0];
    const float* wka = (const float*)d_in[1];
    const float* wkb = (const float*)d_in[2];
    const float* wza = (const float*)d_in[3];
    const float* wzb = (const float*)d_in[4];
    const float* ba  = (const float*)d_in[5];
    const float* bb  = (const float*)d_in[6];
    float* out = (float*)d_out;

    cudaFuncSetAttribute(gemm_kernel,
                         cudaFuncAttributeMaxDynamicSharedMemorySize, SMEM_BYTES);

    prep_w_kernel<<<dim3(D_ / 32, HD_ / 32, 4), dim3(32, 8)>>>(wka, wkb, wza, wzb);
    gemm_kernel<<<(NTOK / BM) * (NCOL / BN), 256, SMEM_BYTES>>>(h);

    int dup = (out_size >= 2 * OUT_ELEMS) ? 1 : 0;
    epilogue_kernel<<<OUT_ELEMS / 4 / 256, 256>>>(ba, bb, out, dup);
}

// round 17
// speedup vs baseline: 1.0179x; 1.0179x over previous
#include <cuda_runtime.h>
#include <cuda_fp16.h>
#include <cstdint>

// ---------------- problem constants -------------------------------------
#define B_    4
#define S_    8192
#define D_    2048
#define HD_   128
#define NTOK  (B_ * S_)            // 32768 tokens
#define NCOL  512                  // 4 projections * HD
#define NBLK  (B_ * (S_ / 4))      // 8192 output blocks
#define OUT_ELEMS (NBLK * HD_)     // 1048576

// GEMM tiling
#define BM 64
#define BN 256
#define BK 64
#define NKC (D_ / BK)              // 32 k-chunks

// ---------------- scratch (static device globals) ------------------------
__device__ __half g_Wt[NCOL * D_];                // 2 MB, K-major fp16 weights
__device__ __half g_C[(size_t)NTOK * NCOL];       // 32 MB GEMM output (fp16)

// ---------------- helpers ------------------------------------------------
__device__ __forceinline__ uint32_t smem_to_u32(const void* p) {
    uint32_t a;
    asm("{ .reg .u64 t; cvta.to.shared.u64 t, %1; cvt.u32.u64 %0, t; }"
        : "=r"(a) : "l"(p));
    return a;
}

// pack (k0, k1) -> f16x2 with k0 in the low half
__device__ __forceinline__ uint32_t pack2(float k0, float k1) {
    uint32_t r;
    asm("cvt.rn.f16x2.f32 %0, %1, %2;" : "=r"(r) : "f"(k1), "f"(k0));
    return r;
}

#define CP_ASYNC16(dst_u32, src_ptr) \
    asm volatile("cp.async.cg.shared.global [%0], [%1], 16;" \
                 :: "r"(dst_u32), "l"(src_ptr) : "memory")
#define CP_ASYNC_COMMIT() asm volatile("cp.async.commit_group;" ::: "memory")
#define CP_ASYNC_WAIT0()  asm volatile("cp.async.wait_group 0;" ::: "memory")

#define MMA_FP16(d, a, b) \
    asm volatile("mma.sync.aligned.m16n8k16.row.col.f32.f16.f16.f32 " \
                 "{%0,%1,%2,%3}, {%4,%5,%6,%7}, {%8,%9}, {%0,%1,%2,%3};" \
                 : "+f"((d)[0]), "+f"((d)[1]), "+f"((d)[2]), "+f"((d)[3]) \
                 : "r"((a)[0]), "r"((a)[1]), "r"((a)[2]), "r"((a)[3]), \
                   "r"((b)[0]), "r"((b)[1]))

#define LDMATRIX_X4(r0, r1, r2, r3, addr) \
    asm volatile("ldmatrix.sync.aligned.m8n8.x4.shared.b16 {%0,%1,%2,%3}, [%4];" \
                 : "=r"(r0), "=r"(r1), "=r"(r2), "=r"(r3) : "r"(addr))

// ---------------- smem layout (bytes): fp16 tiles, 128B rows padded to 144B
#define ROWB    144
#define A_PLANE (64 * ROWB)                // 9216 B
#define B_PLANE (256 * ROWB)               // 36864 B
#define STAGE   (A_PLANE + B_PLANE)        // 46080 B
#define OFF_A   0
#define OFF_B   A_PLANE
#define SMEM_BYTES (2 * STAGE)             // 92160 B
// per-warp writeback staging: 32 rows x 144B = 4608 B (8 warps = 36864 <= SMEM_BYTES)
#define WB_ROWB 144

// ---------------- kernel 1: coalesced fp16 transpose of weights ----------
// g_Wt[n, k] = w_mat[k, j],  n = mat*128 + j
__global__ void prep_w_kernel(const float* __restrict__ wka,
                              const float* __restrict__ wkb,
                              const float* __restrict__ wza,
                              const float* __restrict__ wzb)
{
    __shared__ float tile[32][33];
    const int mat = blockIdx.z;
    const float* w = (mat == 0) ? wka : (mat == 1) ? wkb : (mat == 2) ? wza : wzb;
    const int k0 = blockIdx.x * 32;
    const int j0 = blockIdx.y * 32;
    const int tx = threadIdx.x;       // 0..31
    const int ty = threadIdx.y;       // 0..7

    #pragma unroll
    for (int i = 0; i < 32; i += 8)
        tile[ty + i][tx] = w[(size_t)(k0 + ty + i) * HD_ + j0 + tx];
    __syncthreads();
    #pragma unroll
    for (int i = 0; i < 32; i += 8)
        g_Wt[(size_t)(mat * HD_ + j0 + ty + i) * D_ + k0 + tx] =
            __float2half_rn(tile[tx][ty + i]);
}

// ---------------- kernel 2: pipelined fp16 mma.sync GEMM -----------------
// C[t, 0:512] = h[t, :] @ [Wkva | Wkvb | Wza | Wzb]
__global__ void __launch_bounds__(256, 2)
gemm_kernel(const float* __restrict__ h)
{
    extern __shared__ char sm[];
    const uint32_t smem_base = smem_to_u32(sm);

    const int tid    = threadIdx.x;
    const int lane   = tid & 31;
    const int wid    = tid >> 5;
    const int warp_m = wid >> 2;          // 0..1  (32 rows each)
    const int warp_n = wid & 3;           // 0..3  (64 cols each)

    const int t0 = (int)(blockIdx.x >> 1) * BM;
    const int n0 = (int)(blockIdx.x & 1) * BN;

    // A load coords: thread covers 16 contiguous k, one row
    const int arow = tid >> 2;            // 0..63
    const int akc  = tid & 3;             // 16-element k-chunk within 64
    const float* hrow = h + (size_t)(t0 + arow) * D_ + akc * 16;
    const uint32_t a_sts = (uint32_t)(arow * ROWB + akc * 32);

    uint32_t qa[8];

    // quantize 16 floats from hrow+off into qa
    auto loadquantA = [&](int koff) {
        #pragma unroll
        for (int i = 0; i < 4; ++i) {
            float4 v = *(const float4*)(hrow + koff + i * 4);
            qa[2 * i]     = pack2(v.x, v.y);
            qa[2 * i + 1] = pack2(v.z, v.w);
        }
    };

    // -------- prologue: stage 0 --------
    {
        loadquantA(0);
        #pragma unroll
        for (int j = 0; j < 8; ++j) {
            int e = tid + j * 256;
            int row = e >> 3, kc = e & 7;
            uint32_t dst = smem_base + OFF_B + (uint32_t)(row * ROWB + kc * 16);
            CP_ASYNC16(dst, g_Wt + (size_t)(n0 + row) * D_ + kc * 8);
        }
        CP_ASYNC_COMMIT();
        *(uint4*)(sm + OFF_A + a_sts)      = *(uint4*)(qa);
        *(uint4*)(sm + OFF_A + a_sts + 16) = *(uint4*)(qa + 4);
        CP_ASYNC_WAIT0();
        __syncthreads();
    }

    float acc[2][8][4];
    #pragma unroll
    for (int mt = 0; mt < 2; ++mt)
        #pragma unroll
        for (int nt = 0; nt < 8; ++nt)
            #pragma unroll
            for (int i = 0; i < 4; ++i) acc[mt][nt][i] = 0.0f;

    // ---- ldmatrix per-lane base addresses (stage offset added at use) ----
    const int aL_row = (lane & 7) + 8 * ((lane >> 3) & 1);
    const int aL_off = 16 * ((lane >> 4) & 1);
    uint32_t a_addr[2];
    #pragma unroll
    for (int mt = 0; mt < 2; ++mt)
        a_addr[mt] = smem_base + OFF_A +
                     (uint32_t)((warp_m * 32 + mt * 16 + aL_row) * ROWB + aL_off);

    const int bL_row = (lane & 7) + 8 * ((lane >> 4) & 1);
    const int bL_off = 16 * ((lane >> 3) & 1);
    uint32_t b_addr[4];
    #pragma unroll
    for (int j = 0; j < 4; ++j)
        b_addr[j] = smem_base + OFF_B +
                    (uint32_t)((warp_n * 64 + j * 16 + bL_row) * ROWB + bL_off);

    for (int c = 0; c < NKC; ++c) {
        const int sb = (c & 1) * STAGE;
        const int nb = sb ^ STAGE;

        if (c + 1 < NKC) {
            const int k1 = (c + 1) * BK;
            loadquantA(k1);
            #pragma unroll
            for (int j = 0; j < 8; ++j) {
                int e = tid + j * 256;
                int row = e >> 3, kc = e & 7;
                uint32_t dst = smem_base + nb + OFF_B + (uint32_t)(row * ROWB + kc * 16);
                CP_ASYNC16(dst, g_Wt + (size_t)(n0 + row) * D_ + k1 + kc * 8);
            }
            CP_ASYNC_COMMIT();
        }

        // -------- compute on stage sb: 4 k16-steps --------
        #pragma unroll
        for (int ks = 0; ks < 4; ++ks) {
            const uint32_t ko = (uint32_t)sb + ks * 32;
            uint32_t af[2][4], bf[8][2];
            LDMATRIX_X4(af[0][0], af[0][1], af[0][2], af[0][3], a_addr[0] + ko);
            LDMATRIX_X4(af[1][0], af[1][1], af[1][2], af[1][3], a_addr[1] + ko);
            #pragma unroll
            for (int j = 0; j < 4; ++j)
                LDMATRIX_X4(bf[2 * j][0], bf[2 * j][1],
                            bf[2 * j + 1][0], bf[2 * j + 1][1], b_addr[j] + ko);
            #pragma unroll
            for (int mt = 0; mt < 2; ++mt)
                #pragma unroll
                for (int nt = 0; nt < 8; ++nt)
                    MMA_FP16(acc[mt][nt], af[mt], bf[nt]);
        }

        if (c + 1 < NKC) {
            *(uint4*)(sm + nb + OFF_A + a_sts)      = *(uint4*)(qa);
            *(uint4*)(sm + nb + OFF_A + a_sts + 16) = *(uint4*)(qa + 4);
            CP_ASYNC_WAIT0();
        }
        __syncthreads();
    }

    // -------- writeback: stage through per-warp smem, coalesced STG.128 --
    // each warp owns a 32-row x 64-col fp16 block = 4 KB (+pad) in smem
    {
        char* wbuf = sm + wid * (32 * WB_ROWB);
        const int fr = lane >> 2;
        const int c4 = (lane & 3) * 4;          // byte offset of fp16 pair
        #pragma unroll
        for (int mt = 0; mt < 2; ++mt)
            #pragma unroll
            for (int nt = 0; nt < 8; ++nt) {
                *(uint32_t*)(wbuf + (mt * 16 + fr)     * WB_ROWB + nt * 16 + c4) =
                    pack2(acc[mt][nt][0], acc[mt][nt][1]);
                *(uint32_t*)(wbuf + (mt * 16 + 8 + fr) * WB_ROWB + nt * 16 + c4) =
                    pack2(acc[mt][nt][2], acc[mt][nt][3]);
            }
        __syncwarp();
        const int lrow = lane >> 3;             // 0..3
        const int lseg = (lane & 7) * 16;       // 16B segment within 128B row
        #pragma unroll
        for (int i = 0; i < 8; ++i) {
            int row = i * 4 + lrow;
            uint4 v = *(const uint4*)(wbuf + row * WB_ROWB + lseg);
            *(uint4*)(g_C + (size_t)(t0 + warp_m * 32 + row) * NCOL
                          + n0 + warp_n * 64 + (lane & 7) * 8) = v;
        }
    }
}

// ---------------- kernel 3: masked softmax compression (half2) -----------
// C columns: [0,128)=c_a, [128,256)=c_b, [256,384)=z_a, [384,512)=z_b
__global__ void epilogue_kernel(const float* __restrict__ b_a,
                                const float* __restrict__ b_b,
                                float* __restrict__ out, int dup)
{
    int g2 = blockIdx.x * blockDim.x + threadIdx.x;   // 0..524287 (pairs)
    int d  = (g2 & 63) * 2;    // even feature index
    int bi = g2 >> 6;          // global block id 0..8191
    int i  = bi & 2047;        // block within batch
    int b  = bi >> 11;         // batch
    int t0 = b * S_ + i * 4;   // first token of current block

    float2 logit[8], val[8];
    const bool has_prev = (i > 0);
    #pragma unroll
    for (int j = 0; j < 4; ++j) {
        float2 bb2 = *(const float2*)(b_b + j * 128 + d);
        float2 ba2 = *(const float2*)(b_a + j * 128 + d);
        if (has_prev) {
            const __half* Cp = g_C + (size_t)(t0 - 4 + j) * NCOL;
            float2 z = __half22float2(*(const __half2*)(Cp + 384 + d));
            float2 v = __half22float2(*(const __half2*)(Cp + 128 + d));
            logit[j] = make_float2(z.x + bb2.x, z.y + bb2.y);
            val[j]   = v;
        } else {
            logit[j] = make_float2(-3.0e38f, -3.0e38f);
            val[j]   = make_float2(0.0f, 0.0f);
        }
        const __half* Cc = g_C + (size_t)(t0 + j) * NCOL;
        float2 z = __half22float2(*(const __half2*)(Cc + 256 + d));
        float2 v = __half22float2(*(const __half2*)(Cc + d));
        logit[4 + j] = make_float2(z.x + ba2.x, z.y + ba2.y);
        val[4 + j]   = v;
    }
    float mx0 = logit[0].x, mx1 = logit[0].y;
    #pragma unroll
    for (int j = 1; j < 8; ++j) {
        mx0 = fmaxf(mx0, logit[j].x);
        mx1 = fmaxf(mx1, logit[j].y);
    }
    float s0 = 0.0f, s1 = 0.0f, a0 = 0.0f, a1 = 0.0f;
    #pragma unroll
    for (int j = 0; j < 8; ++j) {
        float e0 = __expf(logit[j].x - mx0);
        float e1 = __expf(logit[j].y - mx1);
        s0 += e0; s1 += e1;
        a0 += e0 * val[j].x; a1 += e1 * val[j].y;
    }
    float2 r = make_float2(a0 / s0, a1 / s1);
    int o = bi * 128 + d;
    *(float2*)(out + o) = r;
    if (dup) *(float2*)(out + o + OUT_ELEMS) = r;
}

// ---------------- launch ------------------------------------------------
extern "C" void kernel_launch(void* const* d_in, const int* in_sizes, int n_in,
                              void* d_out, int out_size)
{
    const float* h   = (const float*)d_in[0];
    const float* wka = (const float*)d_in[1];
    const float* wkb = (const float*)d_in[2];
    const float* wza = (const float*)d_in[3];
    const float* wzb = (const float*)d_in[4];
    const float* ba  = (const float*)d_in[5];
    const float* bb  = (const float*)d_in[6];
    float* out = (float*)d_out;

    cudaFuncSetAttribute(gemm_kernel,
                         cudaFuncAttributeMaxDynamicSharedMemorySize, SMEM_BYTES);

    prep_w_kernel<<<dim3(D_ / 32, HD_ / 32, 4), dim3(32, 8)>>>(wka, wkb, wza, wzb);
    gemm_kernel<<<(NTOK / BM) * (NCOL / BN), 256, SMEM_BYTES>>>(h);

    int dup = (out_size >= 2 * OUT_ELEMS) ? 1 : 0;
    epilogue_kernel<<<OUT_ELEMS / 2 / 256, 256>>>(ba, bb, out, dup);
}